// round 16
// baseline (speedup 1.0000x reference)
#include <cuda_runtime.h>
#include <cuda_bf16.h>
#include <cuda_fp16.h>
#include <math.h>

// ---------------- scratch (device globals; no allocation) ----------------
__device__ float g_gi[12582912];    // 65536 x 384 fp16 (as float storage /2)
__device__ float g_short[8388608];  // 65536 x 128
__device__ float g_WB1[24576];
__device__ float g_WiB[3072];
__device__ float g_WB4[24576];
__device__ float g_WtG[16384];      // gat_intra_W transposed [n][k] fp32
__device__ float g_WtF[49152];      // fusion_w transposed [n][k] fp32 (k=384)
__device__ float g_intra[262144];
__device__ float g_lg[262144];
__device__ float g_la[262144];
__device__ float g_Wh[262144];
__device__ float g_s12[4096];
__device__ float g_secp[32768];
__device__ float g_cntp[256];
__device__ float g_secout[2048];

// ---------------- helpers ----------------
__device__ __forceinline__ float sigmoidf_(float x) {
    return __fdividef(1.f, 1.f + __expf(-x));
}
__device__ __forceinline__ float tanhapx_(float x) {
    float y; asm("tanh.approx.f32 %0, %1;" : "=f"(y) : "f"(x)); return y;
}
__device__ __forceinline__ float sigapx_(float x) {
    return fmaf(tanhapx_(0.5f * x), 0.5f, 0.5f);
}
__device__ __forceinline__ unsigned f2tf(float f) {
    unsigned u; asm("cvt.rna.tf32.f32 %0, %1;" : "=r"(u) : "f"(f)); return u;
}
__device__ __forceinline__ void mma_bf16(float d[4], unsigned a0, unsigned a1,
                                         unsigned a2, unsigned a3,
                                         unsigned b0, unsigned b1) {
    asm volatile(
        "mma.sync.aligned.m16n8k16.row.col.f32.bf16.bf16.f32 "
        "{%0,%1,%2,%3},{%4,%5,%6,%7},{%8,%9},{%0,%1,%2,%3};\n"
        : "+f"(d[0]), "+f"(d[1]), "+f"(d[2]), "+f"(d[3])
        : "r"(a0), "r"(a1), "r"(a2), "r"(a3), "r"(b0), "r"(b1));
}
__device__ __forceinline__ void mma_tf32(float d[4], const unsigned a[4],
                                         unsigned b0, unsigned b1) {
    asm volatile(
        "mma.sync.aligned.m16n8k8.row.col.f32.tf32.tf32.f32 "
        "{%0,%1,%2,%3},{%4,%5,%6,%7},{%8,%9},{%0,%1,%2,%3};\n"
        : "+f"(d[0]), "+f"(d[1]), "+f"(d[2]), "+f"(d[3])
        : "r"(a[0]), "r"(a[1]), "r"(a[2]), "r"(a[3]), "r"(b0), "r"(b1));
}
__device__ __forceinline__ float blockReduceSum128(float v, float* red) {
    #pragma unroll
    for (int o = 16; o; o >>= 1) v += __shfl_xor_sync(0xffffffffu, v, o);
    int w = threadIdx.x >> 5;
    if ((threadIdx.x & 31) == 0) red[w] = v;
    __syncthreads();
    float s = red[0] + red[1] + red[2] + red[3];
    __syncthreads();
    return s;
}

// ---------------- fused weight prep ----------------
__global__ void conv_all(const float* __restrict__ W1, __nv_bfloat16* __restrict__ O1,
                         const float* __restrict__ W2, __nv_bfloat16* __restrict__ O2,
                         const float* __restrict__ W3, __nv_bfloat16* __restrict__ O3,
                         const float* __restrict__ giW, float* __restrict__ WtG,
                         const float* __restrict__ fw, float* __restrict__ WtF) {
    int i = blockIdx.x * 256 + threadIdx.x;
    if (i < 49152) O1[i] = __float2bfloat16(W1[i]);
    if (i < 6144)  O2[i] = __float2bfloat16(W2[i]);
    if (i < 49152) O3[i] = __float2bfloat16(W3[i]);
    if (i < 16384) { int k = i >> 7, n = i & 127; WtG[n * 128 + k] = giW[i]; }
    if (i < 49152) { int k = i / 128, n = i % 128; WtF[n * 384 + k] = fw[i]; }
}

// ---------------- stage-1: dual-batch bf16 GRU + fused pooling, persistent ----------------
__global__ void __launch_bounds__(512, 1) gru1_dual(
    const float* __restrict__ xin,
    const __nv_bfloat16* __restrict__ WiB,
    const __nv_bfloat16* __restrict__ WB,
    const float* __restrict__ bih, const float* __restrict__ bhh,
    const float* __restrict__ aw, const float* __restrict__ ab,
    float* __restrict__ outp, int nPair)
{
    constexpr int T = 5;
    extern __shared__ char smc[];
    __nv_bfloat16* hsm = (__nv_bfloat16*)smc;      // [2][T][16][136]
    __nv_bfloat16* x_b = hsm + 2 * T * 16 * 136;   // [2][16][88]
    float* sc_s = (float*)(x_b + 2 * 16 * 88);     // [2][16][T]

    int tid = threadIdx.x;
    int w = tid >> 5, lane = tid & 31;
    int g = lane >> 2, tig = lane & 3;
    int c0 = w * 8 + 2 * tig;

    unsigned wb[8][3][2];
    #pragma unroll
    for (int kt = 0; kt < 8; kt++) {
        #pragma unroll
        for (int nt = 0; nt < 3; nt++) {
            const __nv_bfloat16* p = WB + (size_t)(nt * 128 + w * 8 + g) * 128 + kt * 16;
            wb[kt][nt][0] = *(const unsigned*)(p + 2 * tig);
            wb[kt][nt][1] = *(const unsigned*)(p + 8 + 2 * tig);
        }
    }
    unsigned wbi[3][2];
    #pragma unroll
    for (int nt = 0; nt < 3; nt++) {
        const __nv_bfloat16* p = WiB + (size_t)(nt * 128 + w * 8 + g) * 16;
        wbi[nt][0] = *(const unsigned*)(p + 2 * tig);
        wbi[nt][1] = *(const unsigned*)(p + 8 + 2 * tig);
    }
    float2 t1, t2;
    t1 = *(const float2*)(bih + c0);       t2 = *(const float2*)(bhh + c0);
    float2 br2 = make_float2(t1.x + t2.x, t1.y + t2.y);
    t1 = *(const float2*)(bih + 128 + c0); t2 = *(const float2*)(bhh + 128 + c0);
    float2 bz2 = make_float2(t1.x + t2.x, t1.y + t2.y);
    float2 bin2 = *(const float2*)(bih + 256 + c0);
    float2 bhn2 = *(const float2*)(bhh + 256 + c0);
    float ab0 = __ldg(ab);
    float awv[4];
    #pragma unroll
    for (int q = 0; q < 4; q++) awv[q] = __ldg(aw + lane + 32 * q);

    float xf[5];
    bool have_pf = false;

    for (int b = blockIdx.x; b < nPair; b += gridDim.x) {
        size_t seq0 = (size_t)b * 32;

        if (!have_pf) {
            for (int i = tid; i < 2560; i += 512) {
                int u = i / 1280, rr = (i % 1280) / 80, col = i % 80;
                x_b[u * (16 * 88) + rr * 88 + col] =
                    __float2bfloat16(__ldg(xin + seq0 * 80 + i));
            }
        } else {
            #pragma unroll
            for (int q = 0; q < 5; q++) {
                int i = tid + q * 512;
                int u = i / 1280, rr = (i % 1280) / 80, col = i % 80;
                x_b[u * (16 * 88) + rr * 88 + col] = __float2bfloat16(xf[q]);
            }
        }
        __syncthreads();

        float hsav[2][2][2];  // [u][hh][elem] — this thread's h from previous step
        for (int t = 0; t < T; t++) {
            float aR[2][4] = {}, aZ[2][4] = {}, aN[2][4] = {}, aI[2][4] = {};
            #pragma unroll
            for (int u = 0; u < 2; u++) {
                const __nv_bfloat16* xb = x_b + u * (16 * 88);
                int kc = t * 16 + 2 * tig;
                unsigned a0 = *(const unsigned*)(xb + g * 88 + kc);
                unsigned a1 = *(const unsigned*)(xb + (g + 8) * 88 + kc);
                unsigned a2 = *(const unsigned*)(xb + g * 88 + kc + 8);
                unsigned a3 = *(const unsigned*)(xb + (g + 8) * 88 + kc + 8);
                mma_bf16(aR[u], a0, a1, a2, a3, wbi[0][0], wbi[0][1]);
                mma_bf16(aZ[u], a0, a1, a2, a3, wbi[1][0], wbi[1][1]);
                mma_bf16(aI[u], a0, a1, a2, a3, wbi[2][0], wbi[2][1]);
            }
            if (t > 0) {
                #pragma unroll
                for (int kt = 0; kt < 8; kt++) {
                    #pragma unroll
                    for (int u = 0; u < 2; u++) {
                        const __nv_bfloat16* hb =
                            hsm + u * (T * 16 * 136) + (t - 1) * (16 * 136);
                        int kc = kt * 16 + 2 * tig;
                        unsigned a0 = *(const unsigned*)(hb + g * 136 + kc);
                        unsigned a1 = *(const unsigned*)(hb + (g + 8) * 136 + kc);
                        unsigned a2 = *(const unsigned*)(hb + g * 136 + kc + 8);
                        unsigned a3 = *(const unsigned*)(hb + (g + 8) * 136 + kc + 8);
                        mma_bf16(aR[u], a0, a1, a2, a3, wb[kt][0][0], wb[kt][0][1]);
                        mma_bf16(aZ[u], a0, a1, a2, a3, wb[kt][1][0], wb[kt][1][1]);
                        mma_bf16(aN[u], a0, a1, a2, a3, wb[kt][2][0], wb[kt][2][1]);
                    }
                }
            }
            #pragma unroll
            for (int u = 0; u < 2; u++) {
                __nv_bfloat16* hcur = hsm + u * (T * 16 * 136) + t * (16 * 136);
                #pragma unroll
                for (int hh = 0; hh < 2; hh++) {
                    int row = hh ? g + 8 : g;
                    int e = hh * 2;
                    float gr0 = aR[u][e] + br2.x, gr1 = aR[u][e + 1] + br2.y;
                    float gz0 = aZ[u][e] + bz2.x, gz1 = aZ[u][e + 1] + bz2.y;
                    float gn0 = aN[u][e] + bhn2.x, gn1 = aN[u][e + 1] + bhn2.y;
                    float in0 = aI[u][e] + bin2.x, in1 = aI[u][e + 1] + bin2.y;
                    float r0 = sigapx_(gr0), r1 = sigapx_(gr1);
                    float z0 = sigapx_(gz0), z1 = sigapx_(gz1);
                    float n0 = tanhapx_(fmaf(r0, gn0, in0));
                    float n1 = tanhapx_(fmaf(r1, gn1, in1));
                    float h0, h1;
                    if (t == 0) {
                        h0 = (1.f - z0) * n0;
                        h1 = (1.f - z1) * n1;
                    } else {
                        // h_prev at (row, c0..c0+1) was computed by this thread
                        float bp0 = __bfloat162float(__float2bfloat16(hsav[u][hh][0]));
                        float bp1 = __bfloat162float(__float2bfloat16(hsav[u][hh][1]));
                        h0 = fmaf(z0, bp0 - n0, n0);
                        h1 = fmaf(z1, bp1 - n1, n1);
                    }
                    hsav[u][hh][0] = h0; hsav[u][hh][1] = h1;
                    *(__nv_bfloat162*)(hcur + row * 136 + c0) =
                        __float22bfloat162_rn(make_float2(h0, h1));
                }
            }
            __syncthreads();
        }

        {
            int bn = b + gridDim.x;
            if (bn < nPair) {
                const float* xp = xin + (size_t)bn * 32 * 80;
                #pragma unroll
                for (int q = 0; q < 5; q++) xf[q] = __ldg(xp + tid + q * 512);
                have_pf = true;
            } else {
                have_pf = false;
            }
        }

        #pragma unroll
        for (int u = 0; u < 2; u++) {
            const __nv_bfloat16* hb = hsm + u * (T * 16 * 136);
            for (int t = 0; t < T; t++) {
                float v = 0.f;
                #pragma unroll
                for (int q = 0; q < 4; q++)
                    v = fmaf(__bfloat162float(hb[t * (16 * 136) + w * 136 + lane + 32 * q]),
                             awv[q], v);
                #pragma unroll
                for (int o = 16; o; o >>= 1) v += __shfl_xor_sync(0xffffffffu, v, o);
                if (lane == 0) sc_s[u * (16 * T) + w * T + t] = v + ab0;
            }
        }
        __syncthreads();
        {
            int j = tid & 127, sb = tid >> 7;
            for (int q = sb; q < 32; q += 4) {
                int u = q >> 4, s = q & 15;
                const __nv_bfloat16* hb = hsm + u * (T * 16 * 136);
                const float* sc = sc_s + u * (16 * T) + s * T;
                float m = -1e30f;
                #pragma unroll
                for (int t = 0; t < T; t++) m = fmaxf(m, sc[t]);
                float Z = 0.f, acc = 0.f;
                #pragma unroll
                for (int t = 0; t < T; t++) {
                    float wt = __expf(sc[t] - m);
                    Z += wt;
                    acc = fmaf(wt, __bfloat162float(hb[t * (16 * 136) + s * 136 + j]), acc);
                }
                outp[(seq0 + u * 16 + s) * 128 + j] = acc / Z;
            }
        }
    }
}

// ---------------- stage-4: bf16 GRU over fp16 gi, fused pooling ----------------
__global__ void __launch_bounds__(512, 1) gru4(
    const __half* __restrict__ gi,
    const __nv_bfloat16* __restrict__ WB,
    const float* __restrict__ bhh,
    const float* __restrict__ aw, const float* __restrict__ ab,
    float* __restrict__ outp)
{
    constexpr int T = 32;
    extern __shared__ char smc[];
    __nv_bfloat16* hsm = (__nv_bfloat16*)smc;
    float* sc_s = (float*)(hsm + T * 16 * 136);

    int tid = threadIdx.x;
    int w = tid >> 5, lane = tid & 31;
    int g = lane >> 2, tig = lane & 3;
    int c0 = w * 8 + 2 * tig;
    size_t seq0 = (size_t)blockIdx.x * 16;

    unsigned wb[8][3][2];
    #pragma unroll
    for (int kt = 0; kt < 8; kt++) {
        #pragma unroll
        for (int nt = 0; nt < 3; nt++) {
            const __nv_bfloat16* p = WB + (size_t)(nt * 128 + w * 8 + g) * 128 + kt * 16;
            wb[kt][nt][0] = *(const unsigned*)(p + 2 * tig);
            wb[kt][nt][1] = *(const unsigned*)(p + 8 + 2 * tig);
        }
    }
    float2 bhr2 = *(const float2*)(bhh + c0);
    float2 bhz2 = *(const float2*)(bhh + 128 + c0);
    float2 bhn2 = *(const float2*)(bhh + 256 + c0);
    float ab0 = __ldg(ab);
    float awv[4];
    #pragma unroll
    for (int q = 0; q < 4; q++) awv[q] = __ldg(aw + lane + 32 * q);
    __syncthreads();

    float hsav[2][2];
    for (int t = 0; t < T; t++) {
        float ra[4] = {0, 0, 0, 0}, rb[4] = {0, 0, 0, 0};
        float za[4] = {0, 0, 0, 0}, zb[4] = {0, 0, 0, 0};
        float na[4] = {0, 0, 0, 0}, nb[4] = {0, 0, 0, 0};
        float2 pgr[2], pgz[2], pgn[2];
        #pragma unroll
        for (int hh = 0; hh < 2; hh++) {
            int row = hh ? g + 8 : g;
            const __half* gp = gi + ((seq0 + row) * (size_t)T + t) * 384;
            pgr[hh] = __half22float2(*(const __half2*)(gp + c0));
            pgz[hh] = __half22float2(*(const __half2*)(gp + 128 + c0));
            pgn[hh] = __half22float2(*(const __half2*)(gp + 256 + c0));
        }
        if (t > 0) {
            const __nv_bfloat16* hb = hsm + (size_t)(t - 1) * 16 * 136;
            #pragma unroll
            for (int kt = 0; kt < 8; kt++) {
                int kc = kt * 16 + 2 * tig;
                unsigned a0 = *(const unsigned*)(hb + g * 136 + kc);
                unsigned a1 = *(const unsigned*)(hb + (g + 8) * 136 + kc);
                unsigned a2 = *(const unsigned*)(hb + g * 136 + kc + 8);
                unsigned a3 = *(const unsigned*)(hb + (g + 8) * 136 + kc + 8);
                if (kt & 1) {
                    mma_bf16(rb, a0, a1, a2, a3, wb[kt][0][0], wb[kt][0][1]);
                    mma_bf16(zb, a0, a1, a2, a3, wb[kt][1][0], wb[kt][1][1]);
                    mma_bf16(nb, a0, a1, a2, a3, wb[kt][2][0], wb[kt][2][1]);
                } else {
                    mma_bf16(ra, a0, a1, a2, a3, wb[kt][0][0], wb[kt][0][1]);
                    mma_bf16(za, a0, a1, a2, a3, wb[kt][1][0], wb[kt][1][1]);
                    mma_bf16(na, a0, a1, a2, a3, wb[kt][2][0], wb[kt][2][1]);
                }
            }
        }
        {
            __nv_bfloat16* hcur = hsm + (size_t)t * 16 * 136;
            #pragma unroll
            for (int hh = 0; hh < 2; hh++) {
                int row = hh ? g + 8 : g;
                int e = hh * 2;
                float gr0 = ra[e] + rb[e] + bhr2.x + pgr[hh].x;
                float gr1 = ra[e + 1] + rb[e + 1] + bhr2.y + pgr[hh].y;
                float gz0 = za[e] + zb[e] + bhz2.x + pgz[hh].x;
                float gz1 = za[e + 1] + zb[e + 1] + bhz2.y + pgz[hh].y;
                float gn0 = na[e] + nb[e] + bhn2.x;
                float gn1 = na[e + 1] + nb[e + 1] + bhn2.y;
                float r0 = sigapx_(gr0), r1 = sigapx_(gr1);
                float z0 = sigapx_(gz0), z1 = sigapx_(gz1);
                float n0 = tanhapx_(fmaf(r0, gn0, pgn[hh].x));
                float n1 = tanhapx_(fmaf(r1, gn1, pgn[hh].y));
                float h0, h1;
                if (t == 0) {
                    h0 = (1.f - z0) * n0;
                    h1 = (1.f - z1) * n1;
                } else {
                    float bp0 = __bfloat162float(__float2bfloat16(hsav[hh][0]));
                    float bp1 = __bfloat162float(__float2bfloat16(hsav[hh][1]));
                    h0 = fmaf(z0, bp0 - n0, n0);
                    h1 = fmaf(z1, bp1 - n1, n1);
                }
                hsav[hh][0] = h0; hsav[hh][1] = h1;
                *(__nv_bfloat162*)(hcur + row * 136 + c0) =
                    __float22bfloat162_rn(make_float2(h0, h1));
            }
        }
        __syncthreads();
    }

    {
        int s = w;
        for (int t = 0; t < T; t++) {
            float v = 0.f;
            #pragma unroll
            for (int q = 0; q < 4; q++)
                v = fmaf(__bfloat162float(hsm[t * 16 * 136 + s * 136 + lane + 32 * q]),
                         awv[q], v);
            #pragma unroll
            for (int o = 16; o; o >>= 1) v += __shfl_xor_sync(0xffffffffu, v, o);
            if (lane == 0) sc_s[s * T + t] = v + ab0;
        }
    }
    __syncthreads();
    {
        int j = tid & 127, sb = tid >> 7;
        #pragma unroll
        for (int i = 0; i < 4; i++) {
            int s = sb + i * 4;
            float m = -1e30f;
            for (int t = 0; t < T; t++) m = fmaxf(m, sc_s[s * T + t]);
            float Z = 0.f, acc = 0.f;
            for (int t = 0; t < T; t++) {
                float wt = __expf(sc_s[s * T + t] - m);
                Z += wt;
                acc = fmaf(wt, __bfloat162float(hsm[t * 16 * 136 + s * 136 + j]), acc);
            }
            outp[(seq0 + s) * 128 + j] = acc / Z;
        }
    }
}

// ---------------- bf16 GEMM -> fp16 gi (stage 4 only) ----------------
__global__ void __launch_bounds__(256) gemm_bf16h(
    const float* __restrict__ A, const float* __restrict__ W,
    const float* __restrict__ bias, __half* __restrict__ C)
{
    extern __shared__ char gsc[];
    __nv_bfloat16* As = (__nv_bfloat16*)gsc;
    __nv_bfloat16* Ws = As + 64 * 136;
    int tid = threadIdx.x;
    size_t m0 = (size_t)blockIdx.x * 64;
    int n0 = blockIdx.y * 64;
    for (int i = tid; i < 2048; i += 256) {
        int r = i >> 5, c4 = (i & 31) * 4;
        float4 av = *(const float4*)(A + (m0 + r) * 128 + c4);
        float4 wv = *(const float4*)(W + (size_t)(n0 + r) * 128 + c4);
        *(__nv_bfloat162*)(As + r * 136 + c4)     = __float22bfloat162_rn(make_float2(av.x, av.y));
        *(__nv_bfloat162*)(As + r * 136 + c4 + 2) = __float22bfloat162_rn(make_float2(av.z, av.w));
        *(__nv_bfloat162*)(Ws + r * 136 + c4)     = __float22bfloat162_rn(make_float2(wv.x, wv.y));
        *(__nv_bfloat162*)(Ws + r * 136 + c4 + 2) = __float22bfloat162_rn(make_float2(wv.z, wv.w));
    }
    __syncthreads();
    int w = tid >> 5, lane = tid & 31;
    int wm = w & 3, wn = w >> 2;
    int g = lane >> 2, tig = lane & 3;
    int mrow = wm * 16, nbase = wn * 32;
    float d[4][4] = {};
    #pragma unroll
    for (int k0 = 0; k0 < 128; k0 += 16) {
        int kc = k0 + 2 * tig;
        unsigned a0 = *(const unsigned*)(As + (mrow + g) * 136 + kc);
        unsigned a1 = *(const unsigned*)(As + (mrow + g + 8) * 136 + kc);
        unsigned a2 = *(const unsigned*)(As + (mrow + g) * 136 + kc + 8);
        unsigned a3 = *(const unsigned*)(As + (mrow + g + 8) * 136 + kc + 8);
        #pragma unroll
        for (int f = 0; f < 4; f++) {
            unsigned b0 = *(const unsigned*)(Ws + (nbase + f * 8 + g) * 136 + kc);
            unsigned b1 = *(const unsigned*)(Ws + (nbase + f * 8 + g) * 136 + kc + 8);
            mma_bf16(d[f], a0, a1, a2, a3, b0, b1);
        }
    }
    #pragma unroll
    for (int f = 0; f < 4; f++) {
        int col = n0 + nbase + f * 8 + 2 * tig;
        float2 b2 = *(const float2*)(bias + col);
        *(__half2*)(C + (m0 + mrow + g) * 384 + col) =
            __floats2half2_rn(d[f][0] + b2.x, d[f][1] + b2.y);
        *(__half2*)(C + (m0 + mrow + g + 8) * 384 + col) =
            __floats2half2_rn(d[f][2] + b2.x, d[f][3] + b2.y);
    }
}

// ---------------- merged: tf32 GEMM Wh = last @ WtG^T + s12 epilogue ----------------
// grid 32, 256 thr; each block: 64 rows x full 128 cols.
__global__ void __launch_bounds__(256) gemm_gat_s12(
    const float* __restrict__ Hin, int rstride,
    const float* __restrict__ Bt, const float* __restrict__ a,
    float* __restrict__ Wh, float* __restrict__ s12, int M)
{
    extern __shared__ float gs[];
    float* As = gs;             // 64 x 132 (later reused as F)
    float* Ws = gs + 64 * 132;  // 128 x 132
    int tid = threadIdx.x;
    size_t m0 = (size_t)blockIdx.x * 64;
    for (int i = tid; i < 2048; i += 256) {
        int r = i >> 5, c4 = (i & 31) * 4;
        float4 av = *(const float4*)(Hin + (m0 + r) * (size_t)rstride + c4);
        av.x = __uint_as_float(f2tf(av.x)); av.y = __uint_as_float(f2tf(av.y));
        av.z = __uint_as_float(f2tf(av.z)); av.w = __uint_as_float(f2tf(av.w));
        *(float4*)(As + r * 132 + c4) = av;
    }
    for (int i = tid; i < 4096; i += 256) {
        int r = i >> 5, c4 = (i & 31) * 4;
        float4 wv = *(const float4*)(Bt + (size_t)r * 128 + c4);
        wv.x = __uint_as_float(f2tf(wv.x)); wv.y = __uint_as_float(f2tf(wv.y));
        wv.z = __uint_as_float(f2tf(wv.z)); wv.w = __uint_as_float(f2tf(wv.w));
        *(float4*)(Ws + r * 132 + c4) = wv;
    }
    __syncthreads();
    int w = tid >> 5, lane = tid & 31;
    int wm = w & 3, wn = w >> 2;
    int g = lane >> 2, tig = lane & 3;
    int mrow = wm * 16;
    float d[8][4] = {};
    #pragma unroll
    for (int k0 = 0; k0 < 128; k0 += 8) {
        unsigned aa[4];
        aa[0] = __float_as_uint(As[(mrow + g) * 132 + k0 + tig]);
        aa[1] = __float_as_uint(As[(mrow + g + 8) * 132 + k0 + tig]);
        aa[2] = __float_as_uint(As[(mrow + g) * 132 + k0 + tig + 4]);
        aa[3] = __float_as_uint(As[(mrow + g + 8) * 132 + k0 + tig + 4]);
        #pragma unroll
        for (int f = 0; f < 8; f++) {
            int nrow = wn * 64 + f * 8 + g;
            unsigned b0 = __float_as_uint(Ws[nrow * 132 + k0 + tig]);
            unsigned b1 = __float_as_uint(Ws[nrow * 132 + k0 + tig + 4]);
            mma_tf32(d[f], aa, b0, b1);
        }
    }
    __syncthreads();  // done reading As; safe to reuse as F
    float* F = As;
    #pragma unroll
    for (int f = 0; f < 8; f++) {
        int col = wn * 64 + f * 8 + 2 * tig;
        F[(mrow + g) * 132 + col] = d[f][0];     F[(mrow + g) * 132 + col + 1] = d[f][1];
        F[(mrow + g + 8) * 132 + col] = d[f][2]; F[(mrow + g + 8) * 132 + col + 1] = d[f][3];
        *(float2*)(Wh + (m0 + mrow + g) * 128 + col) = make_float2(d[f][0], d[f][1]);
        *(float2*)(Wh + (m0 + mrow + g + 8) * 128 + col) = make_float2(d[f][2], d[f][3]);
    }
    __syncthreads();
    // s12: thread t -> row r = t>>2, quarter q = t&3
    {
        int r = tid >> 2, q = tid & 3;
        float s1 = 0.f, s2 = 0.f;
        #pragma unroll 8
        for (int c = q * 32; c < q * 32 + 32; c++) {
            float v = F[r * 132 + c];
            s1 = fmaf(v, __ldg(a + c), s1);
            s2 = fmaf(v, __ldg(a + 128 + c), s2);
        }
        s1 += __shfl_xor_sync(0xffffffffu, s1, 1);
        s1 += __shfl_xor_sync(0xffffffffu, s1, 2);
        s2 += __shfl_xor_sync(0xffffffffu, s2, 1);
        s2 += __shfl_xor_sync(0xffffffffu, s2, 2);
        if (q == 0) { s12[m0 + r] = s1; s12[M + m0 + r] = s2; }
    }
}

// ---------------- merged: stage-3 GEMM (all 384 cols) + GRU-single -> lg ----------------
// grid 32, 256 thr.
__global__ void __launch_bounds__(256) gemm3_lg(
    const float* __restrict__ A, const float* __restrict__ W,
    const float* __restrict__ bias, const float* __restrict__ bhh,
    float* __restrict__ lg)
{
    extern __shared__ char g3c[];
    __nv_bfloat16* As = (__nv_bfloat16*)g3c;       // 64 x 136
    __nv_bfloat16* Ws = As + 64 * 136;             // 64 x 136 (per chunk)
    float* gates = (float*)(Ws + 64 * 136);        // 64 x 392
    int tid = threadIdx.x;
    size_t m0 = (size_t)blockIdx.x * 64;
    for (int i = tid; i < 2048; i += 256) {
        int r = i >> 5, c4 = (i & 31) * 4;
        float4 av = *(const float4*)(A + (m0 + r) * 128 + c4);
        *(__nv_bfloat162*)(As + r * 136 + c4)     = __float22bfloat162_rn(make_float2(av.x, av.y));
        *(__nv_bfloat162*)(As + r * 136 + c4 + 2) = __float22bfloat162_rn(make_float2(av.z, av.w));
    }
    int w = tid >> 5, lane = tid & 31;
    int wm = w & 3, wn = w >> 2;
    int g = lane >> 2, tig = lane & 3;
    int mrow = wm * 16, nbase = wn * 32;
    for (int nc = 0; nc < 6; nc++) {
        int n0 = nc * 64;
        for (int i = tid; i < 2048; i += 256) {
            int r = i >> 5, c4 = (i & 31) * 4;
            float4 wv = *(const float4*)(W + (size_t)(n0 + r) * 128 + c4);
            *(__nv_bfloat162*)(Ws + r * 136 + c4)     = __float22bfloat162_rn(make_float2(wv.x, wv.y));
            *(__nv_bfloat162*)(Ws + r * 136 + c4 + 2) = __float22bfloat162_rn(make_float2(wv.z, wv.w));
        }
        __syncthreads();
        float d[4][4] = {};
        #pragma unroll
        for (int k0 = 0; k0 < 128; k0 += 16) {
            int kc = k0 + 2 * tig;
            unsigned a0 = *(const unsigned*)(As + (mrow + g) * 136 + kc);
            unsigned a1 = *(const unsigned*)(As + (mrow + g + 8) * 136 + kc);
            unsigned a2 = *(const unsigned*)(As + (mrow + g) * 136 + kc + 8);
            unsigned a3 = *(const unsigned*)(As + (mrow + g + 8) * 136 + kc + 8);
            #pragma unroll
            for (int f = 0; f < 4; f++) {
                unsigned b0 = *(const unsigned*)(Ws + (nbase + f * 8 + g) * 136 + kc);
                unsigned b1 = *(const unsigned*)(Ws + (nbase + f * 8 + g) * 136 + kc + 8);
                mma_bf16(d[f], a0, a1, a2, a3, b0, b1);
            }
        }
        #pragma unroll
        for (int f = 0; f < 4; f++) {
            int col = n0 + nbase + f * 8 + 2 * tig;
            float2 b2 = *(const float2*)(bias + col);
            gates[(mrow + g) * 392 + col] = d[f][0] + b2.x;
            gates[(mrow + g) * 392 + col + 1] = d[f][1] + b2.y;
            gates[(mrow + g + 8) * 392 + col] = d[f][2] + b2.x;
            gates[(mrow + g + 8) * 392 + col + 1] = d[f][3] + b2.y;
        }
        __syncthreads();
    }
    // GRU single-step epilogue (h0 = 0, T=1 attn identity)
    for (int i = tid; i < 8192; i += 256) {
        int r = i >> 7, j = i & 127;
        float gr = gates[r * 392 + j];
        float gz = gates[r * 392 + 128 + j];
        float gn = gates[r * 392 + 256 + j];
        float rr = sigmoidf_(gr + __ldg(bhh + j));
        float zz = sigmoidf_(gz + __ldg(bhh + 128 + j));
        float nn = tanhf(gn + rr * __ldg(bhh + 256 + j));
        lg[(m0 + r) * 128 + j] = (1.f - zz) * nn;
    }
}

// ---------------- sector mean partials (phase 1) ----------------
__global__ void __launch_bounds__(128) sector_partial(
    const float* __restrict__ lg, const int* __restrict__ sect,
    float* __restrict__ secp, float* __restrict__ cntp)
{
    int ns = blockIdx.x >> 4, strip = blockIdx.x & 15;
    int d = threadIdx.x;
    float acc = 0.f, c = 0.f;
    #pragma unroll 4
    for (int i = strip * 128; i < strip * 128 + 128; i++) {
        if (__ldg(sect + i) == ns) {
            acc += lg[(size_t)i * 128 + d];
            c += 1.f;
        }
    }
    secp[(size_t)blockIdx.x * 128 + d] = acc;
    if (d == 0) cntp[blockIdx.x] = c;
}

// ---------------- merged: sector_final + inter-GAT prep + inter attention ----------------
// ONE block, 512 threads.
__global__ void __launch_bounds__(512) sector_inter(
    const float* __restrict__ secp, const float* __restrict__ cntp,
    const float* __restrict__ geW, const float* __restrict__ gea,
    const int* __restrict__ adj, float* __restrict__ secout)
{
    __shared__ float sec_s[2048];   // 16 x 128
    __shared__ float wh2_s[2048];
    __shared__ float s1_s[16], s2_s[16];
    int tid = threadIdx.x;
    int w = tid >> 5, lane = tid & 31;
    // phase 1: strip reduction -> sec
    for (int i = tid; i < 2048; i += 512) {
        int ns = i >> 7, d = i & 127;
        float s = 0.f, c = 0.f;
        #pragma unroll
        for (int q = 0; q < 16; q++) {
            s += secp[(size_t)(ns * 16 + q) * 128 + d];
            c += __ldg(cntp + ns * 16 + q);
        }
        sec_s[i] = s / fmaxf(c, 1.f);
    }
    __syncthreads();
    // phase 2: Wh2 = sec @ geW
    for (int i = tid; i < 2048; i += 512) {
        int m = i >> 7, n = i & 127;
        float acc = 0.f;
        #pragma unroll 8
        for (int k = 0; k < 128; k++)
            acc = fmaf(sec_s[m * 128 + k], __ldg(geW + k * 128 + n), acc);
        wh2_s[i] = acc;
    }
    __syncthreads();
    // phase 3: s1/s2 per node (warp m reduces its 128 values)
    {
        int m = w;
        float s1 = 0.f, s2 = 0.f;
        #pragma unroll
        for (int q = 0; q < 4; q++) {
            int n = lane + 32 * q;
            float v = wh2_s[m * 128 + n];
            s1 = fmaf(v, __ldg(gea + n), s1);
            s2 = fmaf(v, __ldg(gea + 128 + n), s2);
        }
        #pragma unroll
        for (int o = 16; o; o >>= 1) {
            s1 += __shfl_xor_sync(0xffffffffu, s1, o);
            s2 += __shfl_xor_sync(0xffffffffu, s2, o);
        }
        if (lane == 0) { s1_s[m] = s1; s2_s[m] = s2; }
    }
    __syncthreads();
    // phase 4: attention (warp i handles node i)
    {
        int i = w;
        float ev = -1e30f;
        if (lane < 16) {
            float v = s1_s[i] + s2_s[lane];
            v = v >= 0.f ? v : 0.2f * v;
            ev = (__ldg(adj + i * 16 + lane) > 0) ? v : -9.0e15f;
        }
        float m = ev;
        #pragma unroll
        for (int o = 8; o; o >>= 1) m = fmaxf(m, __shfl_xor_sync(0xffffffffu, m, o));
        m = __shfl_sync(0xffffffffu, m, 0);
        float wj = (lane < 16) ? __expf(ev - m) : 0.f;
        float Z = wj;
        #pragma unroll
        for (int o = 8; o; o >>= 1) Z += __shfl_xor_sync(0xffffffffu, Z, o);
        Z = __shfl_sync(0xffffffffu, Z, 0);
        float inv = __fdividef(1.f, Z);
        #pragma unroll
        for (int q = 0; q < 4; q++) {
            int d = lane + 32 * q;
            float acc = 0.f;
            #pragma unroll
            for (int j = 0; j < 16; j++) {
                float wjj = __shfl_sync(0xffffffffu, wj, j);
                acc = fmaf(wjj, wh2_s[j * 128 + d], acc);
            }
            acc *= inv;
            secout[i * 128 + d] = acc > 0.f ? acc : expm1f(acc);
        }
    }
}

// ---------------- GAT intra attention ----------------
__global__ void __launch_bounds__(128) gat_intra_attn(
    const float* __restrict__ Wh, const float* __restrict__ s12,
    const int* __restrict__ sect, float* __restrict__ out)
{
    __shared__ float red[4];
    __shared__ int lst[2048];
    __shared__ float wgt[2048];
    __shared__ int cnt;
    int i = blockIdx.x, d = threadIdx.x;
    if (d == 0) cnt = 0;
    __syncthreads();
    int si = __ldg(sect + i);
    for (int j = d; j < 2048; j += 128)
        if (__ldg(sect + j) == si) { int p = atomicAdd(&cnt, 1); lst[p] = j; }
    __syncthreads();
    int n = cnt;
    float s1i = s12[i];
    float lm = -1e30f;
    for (int p = d; p < n; p += 128) {
        float e = s1i + s12[2048 + lst[p]];
        e = e >= 0.f ? e : 0.2f * e;
        lm = fmaxf(lm, e);
    }
    #pragma unroll
    for (int o = 16; o; o >>= 1) lm = fmaxf(lm, __shfl_xor_sync(0xffffffffu, lm, o));
    if ((d & 31) == 0) red[d >> 5] = lm;
    __syncthreads();
    float m = fmaxf(fmaxf(red[0], red[1]), fmaxf(red[2], red[3]));
    __syncthreads();
    float lz = 0.f;
    for (int p = d; p < n; p += 128) {
        float e = s1i + s12[2048 + lst[p]];
        e = e >= 0.f ? e : 0.2f * e;
        float w = __expf(e - m);
        wgt[p] = w;
        lz += w;
    }
    float Z = blockReduceSum128(lz, red);
    float inv = __fdividef(1.f, Z);
    float acc = 0.f;
    #pragma unroll 4
    for (int p = 0; p < n; p++) acc = fmaf(wgt[p], Wh[(size_t)lst[p] * 128 + d], acc);
    acc *= inv;
    out[(size_t)i * 128 + d] = acc > 0.f ? acc : expm1f(acc);
}

// ---------------- merged: fusion GEMM (all 128 cols, 3 K-chunks) + heads ----------------
// grid 32, 256 thr.
__global__ void __launch_bounds__(256) gemm_fusion_heads(
    const float* __restrict__ lg, const float* __restrict__ la,
    const float* __restrict__ secout, const int* __restrict__ sect,
    const float* __restrict__ Bt, const float* __restrict__ fb,
    const float* __restrict__ rw, const float* __restrict__ rb,
    const float* __restrict__ mw, const float* __restrict__ mb,
    float* __restrict__ out)
{
    extern __shared__ float gs[];
    float* As = gs;             // 64 x 132 (later reused as F)
    float* Ws = gs + 64 * 132;  // 128 x 132
    int tid = threadIdx.x;
    size_t m0 = (size_t)blockIdx.x * 64;
    int w = tid >> 5, lane = tid & 31;
    int wm = w & 3, wn = w >> 2;
    int g = lane >> 2, tig = lane & 3;
    int mrow = wm * 16;
    float d[8][4] = {};
    for (int ch = 0; ch < 3; ch++) {
        for (int i = tid; i < 2048; i += 256) {
            int r = i >> 5, c4 = (i & 31) * 4;
            const float* src;
            if (ch == 0)      src = lg + (m0 + r) * 128;
            else if (ch == 1) src = la + (m0 + r) * 128;
            else              src = secout + (size_t)__ldg(sect + m0 + r) * 128;
            float4 av = *(const float4*)(src + c4);
            av.x = __uint_as_float(f2tf(av.x)); av.y = __uint_as_float(f2tf(av.y));
            av.z = __uint_as_float(f2tf(av.z)); av.w = __uint_as_float(f2tf(av.w));
            *(float4*)(As + r * 132 + c4) = av;
        }
        for (int i = tid; i < 4096; i += 256) {
            int r = i >> 5, c4 = (i & 31) * 4;
            float4 wv = *(const float4*)(Bt + (size_t)r * 384 + ch * 128 + c4);
            wv.x = __uint_as_float(f2tf(wv.x)); wv.y = __uint_as_float(f2tf(wv.y));
            wv.z = __uint_as_float(f2tf(wv.z)); wv.w = __uint_as_float(f2tf(wv.w));
            *(float4*)(Ws + r * 132 + c4) = wv;
        }
        __syncthreads();
        #pragma unroll
        for (int k0 = 0; k0 < 128; k0 += 8) {
            unsigned aa[4];
            aa[0] = __float_as_uint(As[(mrow + g) * 132 + k0 + tig]);
            aa[1] = __float_as_uint(As[(mrow + g + 8) * 132 + k0 + tig]);
            aa[2] = __float_as_uint(As[(mrow + g) * 132 + k0 + tig + 4]);
            aa[3] = __float_as_uint(As[(mrow + g + 8) * 132 + k0 + tig + 4]);
            #pragma unroll
            for (int f = 0; f < 8; f++) {
                int nrow = wn * 64 + f * 8 + g;
                unsigned b0 = __float_as_uint(Ws[nrow * 132 + k0 + tig]);
                unsigned b1 = __float_as_uint(Ws[nrow * 132 + k0 + tig + 4]);
                mma_tf32(d[f], aa, b0, b1);
            }
        }
        __syncthreads();
    }
    // write fused tile to smem (reuse As)
    float* F = As;
    #pragma unroll
    for (int f = 0; f < 8; f++) {
        int col = wn * 64 + f * 8 + 2 * tig;
        float2 b2 = *(const float2*)(fb + col);
        F[(mrow + g) * 132 + col] = d[f][0] + b2.x;
        F[(mrow + g) * 132 + col + 1] = d[f][1] + b2.y;
        F[(mrow + g + 8) * 132 + col] = d[f][2] + b2.x;
        F[(mrow + g + 8) * 132 + col + 1] = d[f][3] + b2.y;
    }
    __syncthreads();
    // heads: thread t -> row r = t>>2, quarter q = t&3
    {
        int r = tid >> 2, q = tid & 3;
        float sr = 0.f, sm = 0.f;
        #pragma unroll 8
        for (int c = q * 32; c < q * 32 + 32; c++) {
            float v = F[r * 132 + c];
            sr = fmaf(v, __ldg(rw + c), sr);
            sm = fmaf(v, __ldg(mw + c), sm);
        }
        sr += __shfl_xor_sync(0xffffffffu, sr, 1);
        sr += __shfl_xor_sync(0xffffffffu, sr, 2);
        sm += __shfl_xor_sync(0xffffffffu, sm, 1);
        sm += __shfl_xor_sync(0xffffffffu, sm, 2);
        if (q == 0) {
            out[m0 + r]        = sr + __ldg(rb);
            out[2048 + m0 + r] = sigmoidf_(sm + __ldg(mb));
        }
    }
}

// ---------------- launch ----------------
extern "C" void kernel_launch(void* const* d_in, const int* in_sizes, int n_in,
                              void* d_out, int out_size)
{
    const float* sf    = (const float*)d_in[0];
    const int*   sect  = (const int*)d_in[1];
    const int*   adj   = (const int*)d_in[2];
    const float* g1Wih = (const float*)d_in[3];
    const float* g1Whh = (const float*)d_in[4];
    const float* g1bih = (const float*)d_in[5];
    const float* g1bhh = (const float*)d_in[6];
    const float* a1w   = (const float*)d_in[7];
    const float* a1b   = (const float*)d_in[8];
    const float* giW   = (const float*)d_in[9];
    const float* gia   = (const float*)d_in[10];
    const float* ggWih = (const float*)d_in[11];
    const float* ggWhh = (const float*)d_in[12];
    const float* ggbih = (const float*)d_in[13];
    const float* ggbhh = (const float*)d_in[14];
    const float* agw   = (const float*)d_in[15];
    const float* agb   = (const float*)d_in[16];
    const float* gaWih = (const float*)d_in[17];
    const float* gaWhh = (const float*)d_in[18];
    const float* gabih = (const float*)d_in[19];
    const float* gabhh = (const float*)d_in[20];
    const float* aaw   = (const float*)d_in[21];
    const float* aab   = (const float*)d_in[22];
    const float* geW   = (const float*)d_in[23];
    const float* gea   = (const float*)d_in[24];
    const float* fw    = (const float*)d_in[25];
    const float* fb    = (const float*)d_in[26];
    const float* rw    = (const float*)d_in[27];
    const float* rb    = (const float*)d_in[28];
    const float* mw    = (const float*)d_in[29];
    const float* mb    = (const float*)d_in[30];
    float* out = (float*)d_out;

    float *gif, *shortb, *WB1f, *WiBf, *WB4f, *WtG, *WtF, *intra, *lgv, *lav,
          *Wh, *s12, *secp, *cntp, *secout;
    cudaGetSymbolAddress((void**)&gif, g_gi);
    cudaGetSymbolAddress((void**)&shortb, g_short);
    cudaGetSymbolAddress((void**)&WB1f, g_WB1);
    cudaGetSymbolAddress((void**)&WiBf, g_WiB);
    cudaGetSymbolAddress((void**)&WB4f, g_WB4);
    cudaGetSymbolAddress((void**)&WtG, g_WtG);
    cudaGetSymbolAddress((void**)&WtF, g_WtF);
    cudaGetSymbolAddress((void**)&intra, g_intra);
    cudaGetSymbolAddress((void**)&lgv, g_lg);
    cudaGetSymbolAddress((void**)&lav, g_la);
    cudaGetSymbolAddress((void**)&Wh, g_Wh);
    cudaGetSymbolAddress((void**)&s12, g_s12);
    cudaGetSymbolAddress((void**)&secp, g_secp);
    cudaGetSymbolAddress((void**)&cntp, g_cntp);
    cudaGetSymbolAddress((void**)&secout, g_secout);
    __nv_bfloat16* WB1 = (__nv_bfloat16*)WB1f;
    __nv_bfloat16* WiB = (__nv_bfloat16*)WiBf;
    __nv_bfloat16* WB4 = (__nv_bfloat16*)WB4f;
    __half* gih = (__half*)gif;

    static cudaStream_t sB = nullptr;
    static cudaEvent_t evFork = nullptr, evJoin = nullptr;
    if (!sB) {
        cudaStreamCreate(&sB);
        cudaEventCreateWithFlags(&evFork, cudaEventDisableTiming);
        cudaEventCreateWithFlags(&evJoin, cudaEventDisableTiming);
    }

    const int smem1 = 2 * 5 * 16 * 136 * 2 + 2 * 16 * 88 * 2 + 2 * 16 * 5 * 4;  // 49792
    const int smem4 = 32 * 16 * 136 * 2 + 16 * 32 * 4;                           // 141312
    const int smemG = 2 * 64 * 136 * 2;                                          // 34816
    const int smemW = (64 * 132 + 128 * 132) * 4;                                // 101376
    const int smem3 = 2 * 64 * 136 * 2 + 64 * 392 * 4;                           // 135168
    cudaFuncSetAttribute(gru1_dual,
                         cudaFuncAttributeMaxDynamicSharedMemorySize, smem1);
    cudaFuncSetAttribute(gru4,
                         cudaFuncAttributeMaxDynamicSharedMemorySize, smem4);
    cudaFuncSetAttribute(gemm_gat_s12,
                         cudaFuncAttributeMaxDynamicSharedMemorySize, smemW);
    cudaFuncSetAttribute(gemm_fusion_heads,
                         cudaFuncAttributeMaxDynamicSharedMemorySize, smemW);
    cudaFuncSetAttribute(gemm3_lg,
                         cudaFuncAttributeMaxDynamicSharedMemorySize, smem3);

    conv_all<<<(49152 + 255) / 256, 256>>>(g1Whh, WB1, g1Wih, WiB, gaWhh, WB4,
                                           giW, WtG, fw, WtF);
    gru1_dual<<<148, 512, smem1>>>(
        sf, WiB, WB1, g1bih, g1bhh, a1w, a1b, shortb, 2048);

    // fork: chain B (stage 4, fp16 gi) on stream sB
    cudaEventRecord(evFork, 0);
    cudaStreamWaitEvent(sB, evFork, 0);
    gemm_bf16h<<<dim3(65536 / 64, 6), 256, smemG, sB>>>(shortb, gaWih, gabih, gih);
    gru4<<<128, 512, smem4, sB>>>(gih, WB4, gabhh, aaw, aab, lav);
    cudaEventRecord(evJoin, sB);

    // chain A (stream 0)
    gemm_gat_s12<<<32, 256, smemW>>>(shortb + 31 * 128, 32 * 128, WtG, gia, Wh, s12, 2048);
    gat_intra_attn<<<2048, 128>>>(Wh, s12, sect, intra);
    gemm3_lg<<<32, 256, smem3>>>(intra, ggWih, ggbih, ggbhh, lgv);
    sector_partial<<<256, 128>>>(lgv, sect, secp, cntp);
    sector_inter<<<1, 512>>>(secp, cntp, geW, gea, adj, secout);

    // join: fusion GEMM + heads
    cudaStreamWaitEvent(0, evJoin, 0);
    gemm_fusion_heads<<<32, 256, smemW>>>(lgv, lav, secout, sect, WtF, fb,
                                          rw, rb, mw, mb, out);
}